// round 15
// baseline (speedup 1.0000x reference)
#include <cuda_runtime.h>
#include <cuda_bf16.h>
#include <math.h>
#include <stdint.h>

// AfmoeMoE grouped-GEMM pipeline, bf16 hi/lo split on mma.sync (sm_100 base).
// R15: term-outer MMA ordering (hh block, hl block, lh block) — breaks
// per-accumulator RAW chains and lowers live fragment registers.
#define T 2048
#define H 1024
#define FF 512
#define E 16
#define TOPK 4

// GEMM smem: per stage, A 128 rows x 32 k bf16 (64B rows, XOR-swizzled) hi+lo,
// B 64 rows. chunk' = chunk ^ ((row>>1)&3), 16B chunks, conflict-free ldmatrix.
#define ROWB 64
#define A_PLANE (128 * ROWB)             // 8192
#define B_PLANE (64 * ROWB)              // 4096
#define STG (2 * A_PLANE + 2 * B_PLANE)  // 24576 per stage
#define NSTAGE 3
#define SMEM_BYTES (NSTAGE * STG)        // 73728 (dynamic) -> 3 CTAs/SM

// conversion region sizes (elements)
#define N_X   (T * H)
#define N_W1  (E * 2 * FF * H)
#define N_W2  (E * H * FF)
#define N_S1  (2 * FF * H)
#define N_S2  (H * FF)
#define N_ALL (N_X + N_W1 + N_W2 + N_S1 + N_S2)

// ---------------- scratch (static device globals) ---------------------------
__device__ int   g_cnt[E];
__device__ int   g_list[E * T];
__device__ float g_wlist[E * T];
__device__ float g_ybuf[(size_t)T * TOPK * H];
__device__ float g_sout[(size_t)T * H];
// bf16 hi/lo planes
__device__ __nv_bfloat16 g_xhi[(size_t)N_X],   g_xlo[(size_t)N_X];
__device__ __nv_bfloat16 g_w1hi[(size_t)N_W1], g_w1lo[(size_t)N_W1];
__device__ __nv_bfloat16 g_w2hi[(size_t)N_W2], g_w2lo[(size_t)N_W2];
__device__ __nv_bfloat16 g_s1hi[(size_t)N_S1], g_s1lo[(size_t)N_S1];
__device__ __nv_bfloat16 g_s2hi[(size_t)N_S2], g_s2lo[(size_t)N_S2];
__device__ __nv_bfloat16 g_ahi[(size_t)E * T * FF], g_alo[(size_t)E * T * FF];
__device__ __nv_bfloat16 g_sahi[(size_t)T * FF],    g_salo[(size_t)T * FF];

// ---------------- helpers ----------------------------------------------------
__device__ __forceinline__ uint32_t smem_u32(const void* p) {
    uint32_t a;
    asm("{ .reg .u64 t; cvta.to.shared.u64 t, %1; cvt.u32.u64 %0, t; }"
        : "=r"(a) : "l"(p));
    return a;
}
__device__ __forceinline__ void ldm_x4(uint32_t& r0, uint32_t& r1,
                                       uint32_t& r2, uint32_t& r3, uint32_t a) {
    asm volatile("ldmatrix.sync.aligned.m8n8.x4.shared.b16 {%0,%1,%2,%3}, [%4];"
                 : "=r"(r0), "=r"(r1), "=r"(r2), "=r"(r3) : "r"(a));
}
__device__ __forceinline__ void mma_bf16(float* c, const uint32_t* a, const uint32_t* b) {
    asm volatile(
        "mma.sync.aligned.m16n8k16.row.col.f32.bf16.bf16.f32 "
        "{%0,%1,%2,%3}, {%4,%5,%6,%7}, {%8,%9}, {%0,%1,%2,%3};"
        : "+f"(c[0]), "+f"(c[1]), "+f"(c[2]), "+f"(c[3])
        : "r"(a[0]), "r"(a[1]), "r"(a[2]), "r"(a[3]), "r"(b[0]), "r"(b[1]));
}
#define CP16(dst, src) \
    asm volatile("cp.async.cg.shared.global [%0], [%1], 16;" :: "r"(dst), "l"(src))
#define CP_COMMIT() asm volatile("cp.async.commit_group;")
#define CP_WAIT(n)  asm volatile("cp.async.wait_group %0;" :: "n"(n))

__device__ __forceinline__ float silu_mul(float g, float u) {
    return g / (1.f + expf(-g)) * u;
}
// swizzled byte offset of (row, 16B-chunk cc) within a 64B-row plane
__device__ __forceinline__ uint32_t swz(int row, int cc) {
    return (uint32_t)(row * ROWB) + (uint32_t)((cc ^ ((row >> 1) & 3)) << 4);
}

// ---------------- reset ------------------------------------------------------
__global__ void k_reset() {
    if (threadIdx.x < E) g_cnt[threadIdx.x] = 0;
}

// ---------------- merged fp32 -> bf16 hi/lo conversion ------------------------
__global__ void k_conv_all(const float* __restrict__ x,
                           const float* __restrict__ w1,
                           const float* __restrict__ w2,
                           const float* __restrict__ sw1,
                           const float* __restrict__ sw2) {
    size_t i = ((size_t)blockIdx.x * blockDim.x + threadIdx.x) * 4;
    if (i >= (size_t)N_ALL) return;
    const float* src; __nv_bfloat16 *hi, *lo; size_t off = i;
    if (off < N_X)                 { src = x;   hi = g_xhi;  lo = g_xlo;  }
    else if ((off -= N_X)  < N_W1) { src = w1;  hi = g_w1hi; lo = g_w1lo; }
    else if ((off -= N_W1) < N_W2) { src = w2;  hi = g_w2hi; lo = g_w2lo; }
    else if ((off -= N_W2) < N_S1) { src = sw1; hi = g_s1hi; lo = g_s1lo; }
    else    { off -= N_S1;           src = sw2; hi = g_s2hi; lo = g_s2lo; }

    float4 v = *(const float4*)(src + off);
    __nv_bfloat16 hx = __float2bfloat16(v.x), hy = __float2bfloat16(v.y);
    __nv_bfloat16 hz = __float2bfloat16(v.z), hw = __float2bfloat16(v.w);
    __nv_bfloat162 h0; h0.x = hx; h0.y = hy;
    __nv_bfloat162 h1; h1.x = hz; h1.y = hw;
    __nv_bfloat162 l0, l1;
    l0.x = __float2bfloat16(v.x - __bfloat162float(hx));
    l0.y = __float2bfloat16(v.y - __bfloat162float(hy));
    l1.x = __float2bfloat16(v.z - __bfloat162float(hz));
    l1.y = __float2bfloat16(v.w - __bfloat162float(hw));
    ((__nv_bfloat162*)(hi + off))[0] = h0;
    ((__nv_bfloat162*)(hi + off))[1] = h1;
    ((__nv_bfloat162*)(lo + off))[0] = l0;
    ((__nv_bfloat162*)(lo + off))[1] = l1;
}

// ---------------- gating (gw staged in smem; 8 tokens/block) -----------------
__global__ void k_gate(const float* __restrict__ x,
                       const float* __restrict__ gw,
                       const float* __restrict__ bias) {
    extern __shared__ float sgw[];          // E*H floats = 64KB
    int tid = threadIdx.x;
    for (int i = tid * 4; i < E * H; i += 256 * 4)
        *(float4*)(sgw + i) = *(const float4*)(gw + i);
    __syncthreads();

    int warp = tid >> 5;
    int lane = tid & 31;
    int t = blockIdx.x * 8 + warp;
    if (t >= T) return;
    const float* xr = x + (size_t)t * H;
    float xv[32];
    #pragma unroll
    for (int i = 0; i < 8; i++)
        *(float4*)(xv + i * 4) = *(const float4*)(xr + lane * 4 + i * 128);
    float sc[E];
    #pragma unroll
    for (int e = 0; e < E; e++) {
        const float* g = sgw + e * H;
        float p = 0.f;
        #pragma unroll
        for (int i = 0; i < 8; i++) {
            float4 gv = *(const float4*)(g + lane * 4 + i * 128);
            p += xv[i*4] * gv.x + xv[i*4+1] * gv.y + xv[i*4+2] * gv.z + xv[i*4+3] * gv.w;
        }
        #pragma unroll
        for (int o = 16; o > 0; o >>= 1) p += __shfl_down_sync(0xffffffffu, p, o);
        sc[e] = 1.f / (1.f + expf(-p));
    }
    if (lane == 0) {
        bool used[E];
        #pragma unroll
        for (int e = 0; e < E; e++) used[e] = false;
        int sel[TOPK]; float w[TOPK]; float sum = 0.f;
        for (int k = 0; k < TOPK; k++) {
            float best = -1e30f; int bi = 0;
            for (int e = 0; e < E; e++) {
                float v = sc[e] + bias[e];
                if (!used[e] && v > best) { best = v; bi = e; }
            }
            used[bi] = true; sel[k] = bi; w[k] = sc[bi]; sum += sc[bi];
        }
        float inv = 1.f / fmaxf(sum, 1e-20f);
        for (int k = 0; k < TOPK; k++) {
            int e = sel[k];
            int pos = atomicAdd(&g_cnt[e], 1);
            g_list[e * T + pos]  = t * TOPK + k;
            g_wlist[e * T + pos] = w[k] * inv;
        }
    }
}

// ============================================================================
// GEMM: CTA tile 128x64, warp tile 32x32 (8 warps 4m x 2n), K chunk 32,
// 3-stage cp.async pipeline, ONE syncthreads per chunk, swizzled 64B rows.
// COMPUTE_STAGE is term-outer: hh MMAs, then hl, then lh — each group of 8
// MMAs hits 8 distinct accumulators (no RAW), per-acc term order unchanged.
// ============================================================================
#define LOAD_STAGE(st, k0)                                                     \
    do {                                                                       \
        uint32_t sb = (st) * STG;                                              \
        CP16(aDstH0 + sb, aHsrc + (k0));                                       \
        CP16(aDstH1 + sb, aHsrc + (k0) + 8);                                   \
        CP16(aDstL0 + sb, aLsrc + (k0));                                       \
        CP16(aDstL1 + sb, aLsrc + (k0) + 8);                                   \
        CP16(bDstH + sb,  bHsrc + (k0));                                       \
        CP16(bDstL + sb,  bLsrc + (k0));                                       \
        CP_COMMIT();                                                           \
    } while (0)

#define COMPUTE_STAGE(st)                                                      \
    do {                                                                       \
        uint32_t sb = (st) * STG;                                              \
        _Pragma("unroll")                                                      \
        for (int s = 0; s < 2; s++) {                                          \
            uint32_t ah[2][4], al[2][4], bh[4][2], bl[4][2];                   \
            _Pragma("unroll")                                                  \
            for (int mi = 0; mi < 2; mi++) {                                   \
                uint32_t adr = sA + sb + swz(rowA0 + mi * 16, s * 2 + ccA0);   \
                ldm_x4(ah[mi][0], ah[mi][1], ah[mi][2], ah[mi][3], adr);       \
            }                                                                  \
            _Pragma("unroll")                                                  \
            for (int nj = 0; nj < 2; nj++) {                                   \
                uint32_t adr = sB + sb + swz(rowB0 + nj * 16, s * 2 + ccB0);   \
                ldm_x4(bh[2*nj][0], bh[2*nj][1], bh[2*nj+1][0], bh[2*nj+1][1], adr); \
            }                                                                  \
            _Pragma("unroll")                                                  \
            for (int mi = 0; mi < 2; mi++)                                     \
                _Pragma("unroll")                                              \
                for (int ni = 0; ni < 4; ni++)                                 \
                    mma_bf16(acc[mi][ni], ah[mi], bh[ni]);                     \
            _Pragma("unroll")                                                  \
            for (int nj = 0; nj < 2; nj++) {                                   \
                uint32_t adr = sB + sb + swz(rowB0 + nj * 16, s * 2 + ccB0) + B_PLANE; \
                ldm_x4(bl[2*nj][0], bl[2*nj][1], bl[2*nj+1][0], bl[2*nj+1][1], adr); \
            }                                                                  \
            _Pragma("unroll")                                                  \
            for (int mi = 0; mi < 2; mi++)                                     \
                _Pragma("unroll")                                              \
                for (int ni = 0; ni < 4; ni++)                                 \
                    mma_bf16(acc[mi][ni], ah[mi], bl[ni]);                     \
            _Pragma("unroll")                                                  \
            for (int mi = 0; mi < 2; mi++) {                                   \
                uint32_t adr = sA + sb + swz(rowA0 + mi * 16, s * 2 + ccA0) + A_PLANE; \
                ldm_x4(al[mi][0], al[mi][1], al[mi][2], al[mi][3], adr);       \
            }                                                                  \
            _Pragma("unroll")                                                  \
            for (int mi = 0; mi < 2; mi++)                                     \
                _Pragma("unroll")                                              \
                for (int ni = 0; ni < 4; ni++)                                 \
                    mma_bf16(acc[mi][ni], al[mi], bh[ni]);                     \
        }                                                                      \
    } while (0)

// single-sync 3-stage pipeline:
// wait(stage c landed) -> sync (all warps done with stage (c-1)) ->
// load(c+2) (overwrites stage (c-1)%3) -> compute(c)
#define GEMM_PIPE(NCH)                                                         \
    LOAD_STAGE(0, 0);                                                          \
    LOAD_STAGE(1, 32);                                                         \
    for (int c = 0; c < (NCH); c++) {                                          \
        if (c + 1 < (NCH)) { CP_WAIT(1); } else { CP_WAIT(0); }                \
        __syncthreads();                                                       \
        if (c + 2 < (NCH)) LOAD_STAGE((c + 2) % NSTAGE, (c + 2) * 32);         \
        COMPUTE_STAGE(c % NSTAGE);                                             \
    }

#define ACC_INIT()                                                             \
    float acc[2][4][4];                                                        \
    _Pragma("unroll")                                                          \
    for (int mi = 0; mi < 2; mi++)                                             \
        _Pragma("unroll")                                                      \
        for (int ni = 0; ni < 4; ni++)                                         \
            _Pragma("unroll")                                                  \
            for (int j = 0; j < 4; j++) acc[mi][ni][j] = 0.f;

// common per-thread loader/compute index setup (swizzled)
#define GEMM_IDX_SETUP()                                                       \
    uint32_t sA = smem_u32(sm);                                                \
    uint32_t sB = sA + 2 * A_PLANE;                                            \
    int ra  = tid >> 1;                                                        \
    int ac0 = (tid & 1) * 2;                                                   \
    uint32_t aDstH0 = sA + swz(ra, ac0);                                       \
    uint32_t aDstH1 = sA + swz(ra, ac0 + 1);                                   \
    uint32_t aDstL0 = aDstH0 + A_PLANE;                                        \
    uint32_t aDstL1 = aDstH1 + A_PLANE;                                        \
    int rbw = tid >> 2, bcc = tid & 3;                                         \
    uint32_t bDstH = sB + swz(rbw, bcc);                                       \
    uint32_t bDstL = bDstH + B_PLANE;                                          \
    int rowA0 = wm * 32 + (l & 15);                                            \
    int ccA0  = l >> 4;                                                        \
    int rowB0 = wn * 32 + ((l >> 4) & 1) * 8 + (l & 7);                        \
    int ccB0  = (l >> 3) & 1;

// ---------------- GEMM1: gu = rows @ w1^T (interleaved gate/up), SiLU fused --
// grid.x = 16 mtiles * 16 ftiles; grid.y = E+1 (y==E -> shared expert)
__global__ void __launch_bounds__(256, 3) k_mm1() {
    int e  = blockIdx.y;
    int mt = blockIdx.x >> 4;
    int ft = blockIdx.x & 15;
    bool sh = (e == E);
    int M; const int* list = nullptr;
    const __nv_bfloat16 *Whi, *Wlo; __nv_bfloat16 *AHI, *ALO;
    if (!sh) {
        M = g_cnt[e]; list = g_list + e * T;
        Whi = g_w1hi + (size_t)e * 2 * FF * H;
        Wlo = g_w1lo + (size_t)e * 2 * FF * H;
        AHI = g_ahi + (size_t)e * T * FF;
        ALO = g_alo + (size_t)e * T * FF;
    } else {
        M = T; Whi = g_s1hi; Wlo = g_s1lo; AHI = g_sahi; ALO = g_salo;
    }
    int m0 = mt * 128;
    if (m0 >= M) return;
    int f0 = ft * 32;

    extern __shared__ __align__(16) char sm[];
    int tid = threadIdx.x, l = tid & 31, wid = tid >> 5;
    int wm = wid & 3, wn = wid >> 2;

    GEMM_IDX_SETUP()

    // global sources
    int arow = m0 + ra; if (arow >= M) arow = M - 1;
    int tok = sh ? arow : (list[arow] >> 2);
    const __nv_bfloat16* aHsrc = g_xhi + (size_t)tok * H + (tid & 1) * 16;
    const __nv_bfloat16* aLsrc = g_xlo + (size_t)tok * H + (tid & 1) * 16;
    int fb = f0 + (rbw >> 1);
    int wrow = (rbw & 1) ? (FF + fb) : fb;
    const __nv_bfloat16* bHsrc = Whi + (size_t)wrow * H + bcc * 8;
    const __nv_bfloat16* bLsrc = Wlo + (size_t)wrow * H + bcc * 8;

    ACC_INIT()
    GEMM_PIPE(H / 32)

    #pragma unroll
    for (int mi = 0; mi < 2; mi++) {
        int r0 = m0 + wm * 32 + mi * 16 + (l >> 2);
        int r1 = r0 + 8;
        #pragma unroll
        for (int ni = 0; ni < 4; ni++) {
            int f = f0 + ((wn * 32 + ni * 8 + (l & 3) * 2) >> 1);
            float* c = acc[mi][ni];
            if (r0 < M) {
                float a = silu_mul(c[0], c[1]);
                __nv_bfloat16 h = __float2bfloat16(a);
                AHI[(size_t)r0 * FF + f] = h;
                ALO[(size_t)r0 * FF + f] = __float2bfloat16(a - __bfloat162float(h));
            }
            if (r1 < M) {
                float a = silu_mul(c[2], c[3]);
                __nv_bfloat16 h = __float2bfloat16(a);
                AHI[(size_t)r1 * FF + f] = h;
                ALO[(size_t)r1 * FF + f] = __float2bfloat16(a - __bfloat162float(h));
            }
        }
    }
}

// ---------------- GEMM2: y = act @ w2^T, scaled scatter ----------------------
// grid.x = 16 mtiles * 16 htiles; grid.y = E+1
__global__ void __launch_bounds__(256, 3) k_mm2() {
    int e  = blockIdx.y;
    int mt = blockIdx.x >> 4;
    int ht = blockIdx.x & 15;
    bool sh = (e == E);
    int M; const int* list = nullptr; const float* wl = nullptr;
    const __nv_bfloat16 *Ahi, *Alo, *Whi, *Wlo;
    if (!sh) {
        M = g_cnt[e]; list = g_list + e * T; wl = g_wlist + e * T;
        Ahi = g_ahi + (size_t)e * T * FF;  Alo = g_alo + (size_t)e * T * FF;
        Whi = g_w2hi + (size_t)e * H * FF; Wlo = g_w2lo + (size_t)e * H * FF;
    } else {
        M = T; Ahi = g_sahi; Alo = g_salo; Whi = g_s2hi; Wlo = g_s2lo;
    }
    int m0 = mt * 128;
    if (m0 >= M) return;
    int n0 = ht * 64;

    extern __shared__ __align__(16) char sm[];
    int tid = threadIdx.x, l = tid & 31, wid = tid >> 5;
    int wm = wid & 3, wn = wid >> 2;

    GEMM_IDX_SETUP()

    int arow = m0 + ra; if (arow >= M) arow = M - 1;
    const __nv_bfloat16* aHsrc = Ahi + (size_t)arow * FF + (tid & 1) * 16;
    const __nv_bfloat16* aLsrc = Alo + (size_t)arow * FF + (tid & 1) * 16;
    const __nv_bfloat16* bHsrc = Whi + (size_t)(n0 + rbw) * FF + bcc * 8;
    const __nv_bfloat16* bLsrc = Wlo + (size_t)(n0 + rbw) * FF + bcc * 8;

    ACC_INIT()
    GEMM_PIPE(FF / 32)

    #pragma unroll
    for (int mi = 0; mi < 2; mi++) {
        int r0 = m0 + wm * 32 + mi * 16 + (l >> 2);
        int r1 = r0 + 8;
        float s0 = 1.f, s1 = 1.f;
        float* o0 = g_sout; float* o1 = g_sout;
        if (!sh) {
            if (r0 < M) { s0 = wl[r0]; o0 = g_ybuf + (size_t)list[r0] * H; }
            if (r1 < M) { s1 = wl[r1]; o1 = g_ybuf + (size_t)list[r1] * H; }
        } else {
            o0 = g_sout + (size_t)r0 * H;
            o1 = g_sout + (size_t)r1 * H;
        }
        #pragma unroll
        for (int ni = 0; ni < 4; ni++) {
            int h = n0 + wn * 32 + ni * 8 + (l & 3) * 2;
            float* c = acc[mi][ni];
            if (r0 < M) { o0[h] = s0 * c[0]; o0[h + 1] = s0 * c[1]; }
            if (r1 < M) { o1[h] = s1 * c[2]; o1[h + 1] = s1 * c[3]; }
        }
    }
}

// ---------------- combine ----------------------------------------------------
__global__ void k_combine(float* __restrict__ out) {
    int idx = blockIdx.x * blockDim.x + threadIdx.x;
    if (idx >= T * H) return;
    int t = idx >> 10;
    int h = idx & (H - 1);
    const float* yb = g_ybuf + (size_t)t * TOPK * H + h;
    out[idx] = g_sout[idx] + yb[0] + yb[H] + yb[2 * H] + yb[3 * H];
}

// ---------------- launcher ---------------------------------------------------
extern "C" void kernel_launch(void* const* d_in, const int* in_sizes, int n_in,
                              void* d_out, int out_size) {
    (void)in_sizes; (void)n_in; (void)out_size;
    const float* x    = (const float*)d_in[0];
    const float* gw   = (const float*)d_in[1];
    const float* bias = (const float*)d_in[2];
    const float* w1   = (const float*)d_in[3];
    const float* w2   = (const float*)d_in[4];
    const float* sw1  = (const float*)d_in[5];
    const float* sw2  = (const float*)d_in[6];
    float* out = (float*)d_out;

    cudaFuncSetAttribute(k_mm1, cudaFuncAttributeMaxDynamicSharedMemorySize, SMEM_BYTES);
    cudaFuncSetAttribute(k_mm2, cudaFuncAttributeMaxDynamicSharedMemorySize, SMEM_BYTES);
    cudaFuncSetAttribute(k_gate, cudaFuncAttributeMaxDynamicSharedMemorySize, E * H * 4);

    // launch order: ncu captures launch #4 -> k_mm1 stays in the profiled slot
    k_reset<<<1, 64>>>();                                               // 1
    k_gate<<<T / 8, 256, E * H * 4>>>(x, gw, bias);                     // 2
    k_conv_all<<<(N_ALL / 4 + 511) / 512, 512>>>(x, w1, w2, sw1, sw2);  // 3
    k_mm1<<<dim3(16 * 16, E + 1), 256, SMEM_BYTES>>>();                 // 4 (profiled)
    k_mm2<<<dim3(16 * 16, E + 1), 256, SMEM_BYTES>>>();                 // 5
    k_combine<<<(T * H + 255) / 256, 256>>>(out);                       // 6
}

// round 17
// speedup vs baseline: 1.0596x; 1.0596x over previous
#include <cuda_runtime.h>
#include <cuda_bf16.h>
#include <math.h>
#include <stdint.h>

// AfmoeMoE grouped-GEMM pipeline, bf16 hi/lo split on mma.sync (sm_100 base).
// R16: revert COMPUTE_STAGE to the R14 interleaved order (R15's term-outer
// regressed); combine kernel vectorized to float4.
#define T 2048
#define H 1024
#define FF 512
#define E 16
#define TOPK 4

// GEMM smem: per stage, A 128 rows x 32 k bf16 (64B rows, XOR-swizzled) hi+lo,
// B 64 rows. chunk' = chunk ^ ((row>>1)&3), 16B chunks, conflict-free ldmatrix.
#define ROWB 64
#define A_PLANE (128 * ROWB)             // 8192
#define B_PLANE (64 * ROWB)              // 4096
#define STG (2 * A_PLANE + 2 * B_PLANE)  // 24576 per stage
#define NSTAGE 3
#define SMEM_BYTES (NSTAGE * STG)        // 73728 (dynamic) -> 3 CTAs/SM

// conversion region sizes (elements)
#define N_X   (T * H)
#define N_W1  (E * 2 * FF * H)
#define N_W2  (E * H * FF)
#define N_S1  (2 * FF * H)
#define N_S2  (H * FF)
#define N_ALL (N_X + N_W1 + N_W2 + N_S1 + N_S2)

// ---------------- scratch (static device globals) ---------------------------
__device__ int   g_cnt[E];
__device__ int   g_list[E * T];
__device__ float g_wlist[E * T];
__device__ float g_ybuf[(size_t)T * TOPK * H];
__device__ float g_sout[(size_t)T * H];
// bf16 hi/lo planes
__device__ __nv_bfloat16 g_xhi[(size_t)N_X],   g_xlo[(size_t)N_X];
__device__ __nv_bfloat16 g_w1hi[(size_t)N_W1], g_w1lo[(size_t)N_W1];
__device__ __nv_bfloat16 g_w2hi[(size_t)N_W2], g_w2lo[(size_t)N_W2];
__device__ __nv_bfloat16 g_s1hi[(size_t)N_S1], g_s1lo[(size_t)N_S1];
__device__ __nv_bfloat16 g_s2hi[(size_t)N_S2], g_s2lo[(size_t)N_S2];
__device__ __nv_bfloat16 g_ahi[(size_t)E * T * FF], g_alo[(size_t)E * T * FF];
__device__ __nv_bfloat16 g_sahi[(size_t)T * FF],    g_salo[(size_t)T * FF];

// ---------------- helpers ----------------------------------------------------
__device__ __forceinline__ uint32_t smem_u32(const void* p) {
    uint32_t a;
    asm("{ .reg .u64 t; cvta.to.shared.u64 t, %1; cvt.u32.u64 %0, t; }"
        : "=r"(a) : "l"(p));
    return a;
}
__device__ __forceinline__ void ldm_x4(uint32_t& r0, uint32_t& r1,
                                       uint32_t& r2, uint32_t& r3, uint32_t a) {
    asm volatile("ldmatrix.sync.aligned.m8n8.x4.shared.b16 {%0,%1,%2,%3}, [%4];"
                 : "=r"(r0), "=r"(r1), "=r"(r2), "=r"(r3) : "r"(a));
}
__device__ __forceinline__ void mma_bf16(float* c, const uint32_t* a, const uint32_t* b) {
    asm volatile(
        "mma.sync.aligned.m16n8k16.row.col.f32.bf16.bf16.f32 "
        "{%0,%1,%2,%3}, {%4,%5,%6,%7}, {%8,%9}, {%0,%1,%2,%3};"
        : "+f"(c[0]), "+f"(c[1]), "+f"(c[2]), "+f"(c[3])
        : "r"(a[0]), "r"(a[1]), "r"(a[2]), "r"(a[3]), "r"(b[0]), "r"(b[1]));
}
#define CP16(dst, src) \
    asm volatile("cp.async.cg.shared.global [%0], [%1], 16;" :: "r"(dst), "l"(src))
#define CP_COMMIT() asm volatile("cp.async.commit_group;")
#define CP_WAIT(n)  asm volatile("cp.async.wait_group %0;" :: "n"(n))

__device__ __forceinline__ float silu_mul(float g, float u) {
    return g / (1.f + expf(-g)) * u;
}
// swizzled byte offset of (row, 16B-chunk cc) within a 64B-row plane
__device__ __forceinline__ uint32_t swz(int row, int cc) {
    return (uint32_t)(row * ROWB) + (uint32_t)((cc ^ ((row >> 1) & 3)) << 4);
}

// ---------------- reset ------------------------------------------------------
__global__ void k_reset() {
    if (threadIdx.x < E) g_cnt[threadIdx.x] = 0;
}

// ---------------- merged fp32 -> bf16 hi/lo conversion ------------------------
__global__ void k_conv_all(const float* __restrict__ x,
                           const float* __restrict__ w1,
                           const float* __restrict__ w2,
                           const float* __restrict__ sw1,
                           const float* __restrict__ sw2) {
    size_t i = ((size_t)blockIdx.x * blockDim.x + threadIdx.x) * 4;
    if (i >= (size_t)N_ALL) return;
    const float* src; __nv_bfloat16 *hi, *lo; size_t off = i;
    if (off < N_X)                 { src = x;   hi = g_xhi;  lo = g_xlo;  }
    else if ((off -= N_X)  < N_W1) { src = w1;  hi = g_w1hi; lo = g_w1lo; }
    else if ((off -= N_W1) < N_W2) { src = w2;  hi = g_w2hi; lo = g_w2lo; }
    else if ((off -= N_W2) < N_S1) { src = sw1; hi = g_s1hi; lo = g_s1lo; }
    else    { off -= N_S1;           src = sw2; hi = g_s2hi; lo = g_s2lo; }

    float4 v = *(const float4*)(src + off);
    __nv_bfloat16 hx = __float2bfloat16(v.x), hy = __float2bfloat16(v.y);
    __nv_bfloat16 hz = __float2bfloat16(v.z), hw = __float2bfloat16(v.w);
    __nv_bfloat162 h0; h0.x = hx; h0.y = hy;
    __nv_bfloat162 h1; h1.x = hz; h1.y = hw;
    __nv_bfloat162 l0, l1;
    l0.x = __float2bfloat16(v.x - __bfloat162float(hx));
    l0.y = __float2bfloat16(v.y - __bfloat162float(hy));
    l1.x = __float2bfloat16(v.z - __bfloat162float(hz));
    l1.y = __float2bfloat16(v.w - __bfloat162float(hw));
    ((__nv_bfloat162*)(hi + off))[0] = h0;
    ((__nv_bfloat162*)(hi + off))[1] = h1;
    ((__nv_bfloat162*)(lo + off))[0] = l0;
    ((__nv_bfloat162*)(lo + off))[1] = l1;
}

// ---------------- gating (gw staged in smem; 8 tokens/block) -----------------
__global__ void k_gate(const float* __restrict__ x,
                       const float* __restrict__ gw,
                       const float* __restrict__ bias) {
    extern __shared__ float sgw[];          // E*H floats = 64KB
    int tid = threadIdx.x;
    for (int i = tid * 4; i < E * H; i += 256 * 4)
        *(float4*)(sgw + i) = *(const float4*)(gw + i);
    __syncthreads();

    int warp = tid >> 5;
    int lane = tid & 31;
    int t = blockIdx.x * 8 + warp;
    if (t >= T) return;
    const float* xr = x + (size_t)t * H;
    float xv[32];
    #pragma unroll
    for (int i = 0; i < 8; i++)
        *(float4*)(xv + i * 4) = *(const float4*)(xr + lane * 4 + i * 128);
    float sc[E];
    #pragma unroll
    for (int e = 0; e < E; e++) {
        const float* g = sgw + e * H;
        float p = 0.f;
        #pragma unroll
        for (int i = 0; i < 8; i++) {
            float4 gv = *(const float4*)(g + lane * 4 + i * 128);
            p += xv[i*4] * gv.x + xv[i*4+1] * gv.y + xv[i*4+2] * gv.z + xv[i*4+3] * gv.w;
        }
        #pragma unroll
        for (int o = 16; o > 0; o >>= 1) p += __shfl_down_sync(0xffffffffu, p, o);
        sc[e] = 1.f / (1.f + expf(-p));
    }
    if (lane == 0) {
        bool used[E];
        #pragma unroll
        for (int e = 0; e < E; e++) used[e] = false;
        int sel[TOPK]; float w[TOPK]; float sum = 0.f;
        for (int k = 0; k < TOPK; k++) {
            float best = -1e30f; int bi = 0;
            for (int e = 0; e < E; e++) {
                float v = sc[e] + bias[e];
                if (!used[e] && v > best) { best = v; bi = e; }
            }
            used[bi] = true; sel[k] = bi; w[k] = sc[bi]; sum += sc[bi];
        }
        float inv = 1.f / fmaxf(sum, 1e-20f);
        for (int k = 0; k < TOPK; k++) {
            int e = sel[k];
            int pos = atomicAdd(&g_cnt[e], 1);
            g_list[e * T + pos]  = t * TOPK + k;
            g_wlist[e * T + pos] = w[k] * inv;
        }
    }
}

// ============================================================================
// GEMM: CTA tile 128x64, warp tile 32x32 (8 warps 4m x 2n), K chunk 32,
// 3-stage cp.async pipeline, ONE syncthreads per chunk, swizzled 64B rows.
// COMPUTE_STAGE: R14 interleaved order (proven fastest; term-outer regressed).
// ============================================================================
#define LOAD_STAGE(st, k0)                                                     \
    do {                                                                       \
        uint32_t sb = (st) * STG;                                              \
        CP16(aDstH0 + sb, aHsrc + (k0));                                       \
        CP16(aDstH1 + sb, aHsrc + (k0) + 8);                                   \
        CP16(aDstL0 + sb, aLsrc + (k0));                                       \
        CP16(aDstL1 + sb, aLsrc + (k0) + 8);                                   \
        CP16(bDstH + sb,  bHsrc + (k0));                                       \
        CP16(bDstL + sb,  bLsrc + (k0));                                       \
        CP_COMMIT();                                                           \
    } while (0)

#define COMPUTE_STAGE(st)                                                      \
    do {                                                                       \
        uint32_t sb = (st) * STG;                                              \
        _Pragma("unroll")                                                      \
        for (int s = 0; s < 2; s++) {                                          \
            uint32_t ah[2][4], al[2][4], bh[4][2], bl[4][2];                   \
            _Pragma("unroll")                                                  \
            for (int mi = 0; mi < 2; mi++) {                                   \
                int rw = rowA0 + mi * 16;                                      \
                uint32_t adr = sA + sb + swz(rw, s * 2 + ccA0);                \
                ldm_x4(ah[mi][0], ah[mi][1], ah[mi][2], ah[mi][3], adr);       \
                ldm_x4(al[mi][0], al[mi][1], al[mi][2], al[mi][3], adr + A_PLANE); \
            }                                                                  \
            _Pragma("unroll")                                                  \
            for (int nj = 0; nj < 2; nj++) {                                   \
                int rw = rowB0 + nj * 16;                                      \
                uint32_t adr = sB + sb + swz(rw, s * 2 + ccB0);                \
                ldm_x4(bh[2*nj][0], bh[2*nj][1], bh[2*nj+1][0], bh[2*nj+1][1], adr); \
                ldm_x4(bl[2*nj][0], bl[2*nj][1], bl[2*nj+1][0], bl[2*nj+1][1], adr + B_PLANE); \
            }                                                                  \
            _Pragma("unroll")                                                  \
            for (int mi = 0; mi < 2; mi++)                                     \
                _Pragma("unroll")                                              \
                for (int ni = 0; ni < 4; ni++) {                               \
                    mma_bf16(acc[mi][ni], ah[mi], bh[ni]);                     \
                    mma_bf16(acc[mi][ni], ah[mi], bl[ni]);                     \
                    mma_bf16(acc[mi][ni], al[mi], bh[ni]);                     \
                }                                                              \
        }                                                                      \
    } while (0)

// single-sync 3-stage pipeline:
// wait(stage c landed) -> sync (all warps done with stage (c-1)) ->
// load(c+2) (overwrites stage (c-1)%3) -> compute(c)
#define GEMM_PIPE(NCH)                                                         \
    LOAD_STAGE(0, 0);                                                          \
    LOAD_STAGE(1, 32);                                                         \
    for (int c = 0; c < (NCH); c++) {                                          \
        if (c + 1 < (NCH)) { CP_WAIT(1); } else { CP_WAIT(0); }                \
        __syncthreads();                                                       \
        if (c + 2 < (NCH)) LOAD_STAGE((c + 2) % NSTAGE, (c + 2) * 32);         \
        COMPUTE_STAGE(c % NSTAGE);                                             \
    }

#define ACC_INIT()                                                             \
    float acc[2][4][4];                                                        \
    _Pragma("unroll")                                                          \
    for (int mi = 0; mi < 2; mi++)                                             \
        _Pragma("unroll")                                                      \
        for (int ni = 0; ni < 4; ni++)                                         \
            _Pragma("unroll")                                                  \
            for (int j = 0; j < 4; j++) acc[mi][ni][j] = 0.f;

// common per-thread loader/compute index setup (swizzled)
#define GEMM_IDX_SETUP()                                                       \
    uint32_t sA = smem_u32(sm);                                                \
    uint32_t sB = sA + 2 * A_PLANE;                                            \
    int ra  = tid >> 1;                                                        \
    int ac0 = (tid & 1) * 2;                                                   \
    uint32_t aDstH0 = sA + swz(ra, ac0);                                       \
    uint32_t aDstH1 = sA + swz(ra, ac0 + 1);                                   \
    uint32_t aDstL0 = aDstH0 + A_PLANE;                                        \
    uint32_t aDstL1 = aDstH1 + A_PLANE;                                        \
    int rbw = tid >> 2, bcc = tid & 3;                                         \
    uint32_t bDstH = sB + swz(rbw, bcc);                                       \
    uint32_t bDstL = bDstH + B_PLANE;                                          \
    int rowA0 = wm * 32 + (l & 15);                                            \
    int ccA0  = l >> 4;                                                        \
    int rowB0 = wn * 32 + ((l >> 4) & 1) * 8 + (l & 7);                        \
    int ccB0  = (l >> 3) & 1;

// ---------------- GEMM1: gu = rows @ w1^T (interleaved gate/up), SiLU fused --
// grid.x = 16 mtiles * 16 ftiles; grid.y = E+1 (y==E -> shared expert)
__global__ void __launch_bounds__(256, 3) k_mm1() {
    int e  = blockIdx.y;
    int mt = blockIdx.x >> 4;
    int ft = blockIdx.x & 15;
    bool sh = (e == E);
    int M; const int* list = nullptr;
    const __nv_bfloat16 *Whi, *Wlo; __nv_bfloat16 *AHI, *ALO;
    if (!sh) {
        M = g_cnt[e]; list = g_list + e * T;
        Whi = g_w1hi + (size_t)e * 2 * FF * H;
        Wlo = g_w1lo + (size_t)e * 2 * FF * H;
        AHI = g_ahi + (size_t)e * T * FF;
        ALO = g_alo + (size_t)e * T * FF;
    } else {
        M = T; Whi = g_s1hi; Wlo = g_s1lo; AHI = g_sahi; ALO = g_salo;
    }
    int m0 = mt * 128;
    if (m0 >= M) return;
    int f0 = ft * 32;

    extern __shared__ __align__(16) char sm[];
    int tid = threadIdx.x, l = tid & 31, wid = tid >> 5;
    int wm = wid & 3, wn = wid >> 2;

    GEMM_IDX_SETUP()

    // global sources
    int arow = m0 + ra; if (arow >= M) arow = M - 1;
    int tok = sh ? arow : (list[arow] >> 2);
    const __nv_bfloat16* aHsrc = g_xhi + (size_t)tok * H + (tid & 1) * 16;
    const __nv_bfloat16* aLsrc = g_xlo + (size_t)tok * H + (tid & 1) * 16;
    int fb = f0 + (rbw >> 1);
    int wrow = (rbw & 1) ? (FF + fb) : fb;
    const __nv_bfloat16* bHsrc = Whi + (size_t)wrow * H + bcc * 8;
    const __nv_bfloat16* bLsrc = Wlo + (size_t)wrow * H + bcc * 8;

    ACC_INIT()
    GEMM_PIPE(H / 32)

    #pragma unroll
    for (int mi = 0; mi < 2; mi++) {
        int r0 = m0 + wm * 32 + mi * 16 + (l >> 2);
        int r1 = r0 + 8;
        #pragma unroll
        for (int ni = 0; ni < 4; ni++) {
            int f = f0 + ((wn * 32 + ni * 8 + (l & 3) * 2) >> 1);
            float* c = acc[mi][ni];
            if (r0 < M) {
                float a = silu_mul(c[0], c[1]);
                __nv_bfloat16 h = __float2bfloat16(a);
                AHI[(size_t)r0 * FF + f] = h;
                ALO[(size_t)r0 * FF + f] = __float2bfloat16(a - __bfloat162float(h));
            }
            if (r1 < M) {
                float a = silu_mul(c[2], c[3]);
                __nv_bfloat16 h = __float2bfloat16(a);
                AHI[(size_t)r1 * FF + f] = h;
                ALO[(size_t)r1 * FF + f] = __float2bfloat16(a - __bfloat162float(h));
            }
        }
    }
}

// ---------------- GEMM2: y = act @ w2^T, scaled scatter ----------------------
// grid.x = 16 mtiles * 16 htiles; grid.y = E+1
__global__ void __launch_bounds__(256, 3) k_mm2() {
    int e  = blockIdx.y;
    int mt = blockIdx.x >> 4;
    int ht = blockIdx.x & 15;
    bool sh = (e == E);
    int M; const int* list = nullptr; const float* wl = nullptr;
    const __nv_bfloat16 *Ahi, *Alo, *Whi, *Wlo;
    if (!sh) {
        M = g_cnt[e]; list = g_list + e * T; wl = g_wlist + e * T;
        Ahi = g_ahi + (size_t)e * T * FF;  Alo = g_alo + (size_t)e * T * FF;
        Whi = g_w2hi + (size_t)e * H * FF; Wlo = g_w2lo + (size_t)e * H * FF;
    } else {
        M = T; Ahi = g_sahi; Alo = g_salo; Whi = g_s2hi; Wlo = g_s2lo;
    }
    int m0 = mt * 128;
    if (m0 >= M) return;
    int n0 = ht * 64;

    extern __shared__ __align__(16) char sm[];
    int tid = threadIdx.x, l = tid & 31, wid = tid >> 5;
    int wm = wid & 3, wn = wid >> 2;

    GEMM_IDX_SETUP()

    int arow = m0 + ra; if (arow >= M) arow = M - 1;
    const __nv_bfloat16* aHsrc = Ahi + (size_t)arow * FF + (tid & 1) * 16;
    const __nv_bfloat16* aLsrc = Alo + (size_t)arow * FF + (tid & 1) * 16;
    const __nv_bfloat16* bHsrc = Whi + (size_t)(n0 + rbw) * FF + bcc * 8;
    const __nv_bfloat16* bLsrc = Wlo + (size_t)(n0 + rbw) * FF + bcc * 8;

    ACC_INIT()
    GEMM_PIPE(FF / 32)

    #pragma unroll
    for (int mi = 0; mi < 2; mi++) {
        int r0 = m0 + wm * 32 + mi * 16 + (l >> 2);
        int r1 = r0 + 8;
        float s0 = 1.f, s1 = 1.f;
        float* o0 = g_sout; float* o1 = g_sout;
        if (!sh) {
            if (r0 < M) { s0 = wl[r0]; o0 = g_ybuf + (size_t)list[r0] * H; }
            if (r1 < M) { s1 = wl[r1]; o1 = g_ybuf + (size_t)list[r1] * H; }
        } else {
            o0 = g_sout + (size_t)r0 * H;
            o1 = g_sout + (size_t)r1 * H;
        }
        #pragma unroll
        for (int ni = 0; ni < 4; ni++) {
            int h = n0 + wn * 32 + ni * 8 + (l & 3) * 2;
            float* c = acc[mi][ni];
            if (r0 < M) { o0[h] = s0 * c[0]; o0[h + 1] = s0 * c[1]; }
            if (r1 < M) { o1[h] = s1 * c[2]; o1[h + 1] = s1 * c[3]; }
        }
    }
}

// ---------------- combine (float4 vectorized) --------------------------------
__global__ void k_combine(float* __restrict__ out) {
    int idx = (blockIdx.x * blockDim.x + threadIdx.x) * 4;
    if (idx >= T * H) return;
    int t = idx >> 10;          // H == 1024
    int h = idx & (H - 1);
    const float* yb = g_ybuf + (size_t)t * TOPK * H + h;
    float4 s  = *(const float4*)(g_sout + idx);
    float4 y0 = *(const float4*)(yb);
    float4 y1 = *(const float4*)(yb + H);
    float4 y2 = *(const float4*)(yb + 2 * H);
    float4 y3 = *(const float4*)(yb + 3 * H);
    float4 r;
    r.x = s.x + y0.x + y1.x + y2.x + y3.x;
    r.y = s.y + y0.y + y1.y + y2.y + y3.y;
    r.z = s.z + y0.z + y1.z + y2.z + y3.z;
    r.w = s.w + y0.w + y1.w + y2.w + y3.w;
    *(float4*)(out + idx) = r;
}

// ---------------- launcher ---------------------------------------------------
extern "C" void kernel_launch(void* const* d_in, const int* in_sizes, int n_in,
                              void* d_out, int out_size) {
    (void)in_sizes; (void)n_in; (void)out_size;
    const float* x    = (const float*)d_in[0];
    const float* gw   = (const float*)d_in[1];
    const float* bias = (const float*)d_in[2];
    const float* w1   = (const float*)d_in[3];
    const float* w2   = (const float*)d_in[4];
    const float* sw1  = (const float*)d_in[5];
    const float* sw2  = (const float*)d_in[6];
    float* out = (float*)d_out;

    cudaFuncSetAttribute(k_mm1, cudaFuncAttributeMaxDynamicSharedMemorySize, SMEM_BYTES);
    cudaFuncSetAttribute(k_mm2, cudaFuncAttributeMaxDynamicSharedMemorySize, SMEM_BYTES);
    cudaFuncSetAttribute(k_gate, cudaFuncAttributeMaxDynamicSharedMemorySize, E * H * 4);

    // launch order: ncu captures launch #4 -> k_mm1 stays in the profiled slot
    k_reset<<<1, 64>>>();                                               // 1
    k_gate<<<T / 8, 256, E * H * 4>>>(x, gw, bias);                     // 2
    k_conv_all<<<(N_ALL / 4 + 511) / 512, 512>>>(x, w1, w2, sw1, sw2);  // 3
    k_mm1<<<dim3(16 * 16, E + 1), 256, SMEM_BYTES>>>();                 // 4 (profiled)
    k_mm2<<<dim3(16 * 16, E + 1), 256, SMEM_BYTES>>>();                 // 5
    k_combine<<<(T * H / 4 + 255) / 256, 256>>>(out);                   // 6
}